// round 3
// baseline (speedup 1.0000x reference)
#include <cuda_runtime.h>
#include <cuda_bf16.h>

#define FULL_MASK 0xFFFFFFFFu
#define TAGS 32
#define START 30
#define STOP 31

__device__ float g_partial[2048];
__device__ int   g_order[2048];
__device__ int   g_count = 0;

// Counting sort of batch ids by descending length (deterministic output set;
// per-batch results are indexed by batch id so final sum is order-invariant).
__global__ void sort_kernel(const int* __restrict__ lens, int B, int L)
{
    __shared__ int scan[1032];
    __shared__ int offs[1032];
    int tid = threadIdx.x;
    int nb = L + 1;
    if (L > 1023) {                 // fallback: identity order
        for (int b = tid; b < B; b += blockDim.x) g_order[b] = b;
        return;
    }
    for (int i = tid; i < nb; i += blockDim.x) scan[i] = 0;
    __syncthreads();
    for (int b = tid; b < B; b += blockDim.x)
        atomicAdd(&scan[L - lens[b]], 1);          // key = descending length
    __syncthreads();
    for (int off = 1; off < nb; off <<= 1) {       // Hillis-Steele inclusive scan
        int v = 0;
        if (tid < nb && tid >= off) v = scan[tid - off];
        __syncthreads();
        if (tid < nb && tid >= off) scan[tid] += v;
        __syncthreads();
    }
    if (tid < nb) offs[tid] = (tid == 0) ? 0 : scan[tid - 1];
    __syncthreads();
    for (int b = tid; b < B; b += blockDim.x) {
        int pos = atomicAdd(&offs[L - lens[b]], 1);
        g_order[pos] = b;
    }
}

// One warp processes TWO batches (independent chains -> 2x ILP per warp).
__global__ void crf_nll_kernel(const float* __restrict__ feats,
                               const float* __restrict__ trans,
                               const int*   __restrict__ tags,
                               const int*   __restrict__ lens,
                               float* __restrict__ out,
                               int B, int L)
{
    __shared__ __align__(16) float buf[2][2][TAGS];

    int lane = threadIdx.x;
    int bA = g_order[2 * blockIdx.x];
    int bB = g_order[2 * blockIdx.x + 1];

    const float* fA = feats + (size_t)bA * L * TAGS;
    const float* fB = feats + (size_t)bB * L * TAGS;
    int lenA = lens[bA];
    int lenB = lens[bB];
    int lmax = max(lenA, lenB);

    // lane j holds E column j: E[i] = exp(trans[i][j])
    float E[TAGS];
#pragma unroll
    for (int i = 0; i < TAGS; ++i)
        E[i] = __expf(trans[i * TAGS + lane]);
    float estop = __expf(trans[lane * TAGS + STOP]);
    float tstart = trans[START * TAGS + lane];

    // alpha0 -> exp-domain, rescaled by lane-0 value (spread bounded, safe)
    float aA = tstart + fA[lane];
    float aB = tstart + fB[lane];
    float mA = __shfl_sync(FULL_MASK, aA, 0);
    float mB = __shfl_sync(FULL_MASK, aB, 0);
    float pA = __expf(aA - mA), lsA = mA;
    float pB = __expf(aB - mB), lsB = mB;

    // feat prefetch rings (4 deep, per batch)
    float qA0 = (1 < lenA) ? fA[1 * TAGS + lane] : 0.f;
    float qA1 = (2 < lenA) ? fA[2 * TAGS + lane] : 0.f;
    float qA2 = (3 < lenA) ? fA[3 * TAGS + lane] : 0.f;
    float qA3 = (4 < lenA) ? fA[4 * TAGS + lane] : 0.f;
    float qB0 = (1 < lenB) ? fB[1 * TAGS + lane] : 0.f;
    float qB1 = (2 < lenB) ? fB[2 * TAGS + lane] : 0.f;
    float qB2 = (3 < lenB) ? fB[3 * TAGS + lane] : 0.f;
    float qB3 = (4 < lenB) ? fB[4 * TAGS + lane] : 0.f;

    for (int t = 1; t < lmax; ++t) {
        float feA = __expf(qA0);
        float feB = __expf(qB0);
        qA0 = qA1; qA1 = qA2; qA2 = qA3;
        qB0 = qB1; qB1 = qB2; qB2 = qB3;
        qA3 = (t + 4 < lenA) ? fA[(t + 4) * TAGS + lane] : 0.f;
        qB3 = (t + 4 < lenB) ? fB[(t + 4) * TAGS + lane] : 0.f;

        int s = t & 1;
        buf[s][0][lane] = pA;
        buf[s][1][lane] = pB;
        __syncwarp();
        const float4* bpA = (const float4*)buf[s][0];
        const float4* bpB = (const float4*)buf[s][1];

        // 8 accumulators each: depth-4 FMA chains + depth-3 combine
        float cA[8], cB[8];
#pragma unroll
        for (int k = 0; k < 8; ++k) {
            float4 qa = bpA[k];
            float4 qb = bpB[k];
            cA[k] = fmaf(qa.w, E[4*k+3], fmaf(qa.z, E[4*k+2],
                     fmaf(qa.y, E[4*k+1], qa.x * E[4*k])));
            cB[k] = fmaf(qb.w, E[4*k+3], fmaf(qb.z, E[4*k+2],
                     fmaf(qb.y, E[4*k+1], qb.x * E[4*k])));
        }
        float sA = ((cA[0]+cA[1]) + (cA[2]+cA[3])) + ((cA[4]+cA[5]) + (cA[6]+cA[7]));
        float sB = ((cB[0]+cB[1]) + (cB[2]+cB[3])) + ((cB[4]+cB[5]) + (cB[6]+cB[7]));

        pA = (t < lenA) ? sA * feA : pA;     // freeze finished batch
        pB = (t < lenB) ? sB * feB : pB;

        // renorm every 4 steps by lane-0 value (rescale-invariant for frozen p)
        if ((t & 3) == 0) {
            float m0A = __shfl_sync(FULL_MASK, pA, 0);
            float m0B = __shfl_sync(FULL_MASK, pB, 0);
            pA *= (1.0f / m0A);  lsA += __logf(m0A);
            pB *= (1.0f / m0B);  lsB += __logf(m0B);
        }
    }

    // forward scores
    float vA = pA * estop;
    float vB = pB * estop;
#pragma unroll
    for (int o = 16; o; o >>= 1) {
        vA += __shfl_xor_sync(FULL_MASK, vA, o);
        vB += __shfl_xor_sync(FULL_MASK, vB, o);
    }
    float fwdA = lsA + __logf(vA);
    float fwdB = lsB + __logf(vB);

    // gold scores (lane-strided gathers)
    const int* tA = tags + (size_t)bA * L;
    const int* tB = tags + (size_t)bB * L;
    float gA = 0.f, gB = 0.f;
    for (int t = lane; t < lenA - 1; t += 32) {
        int u = tA[t], w = tA[t + 1];
        gA += trans[u * TAGS + w] + fA[(t + 1) * TAGS + w];
    }
    for (int t = lane; t < lenB - 1; t += 32) {
        int u = tB[t], w = tB[t + 1];
        gB += trans[u * TAGS + w] + fB[(t + 1) * TAGS + w];
    }
#pragma unroll
    for (int o = 16; o; o >>= 1) {
        gA += __shfl_xor_sync(FULL_MASK, gA, o);
        gB += __shfl_xor_sync(FULL_MASK, gB, o);
    }

    if (lane == 0) {
        int a0 = tA[0], aE = tA[lenA - 1];
        int b0 = tB[0], bE = tB[lenB - 1];
        g_partial[bA] = fwdA - (trans[START * TAGS + a0] + fA[a0]
                                + trans[aE * TAGS + STOP] + gA);
        g_partial[bB] = fwdB - (trans[START * TAGS + b0] + fB[b0]
                                + trans[bE * TAGS + STOP] + gB);
    }

    // fused deterministic final reduction (last block)
    __threadfence();
    int old = 0;
    if (lane == 0) old = atomicAdd(&g_count, 1);
    old = __shfl_sync(FULL_MASK, old, 0);
    if (old == (int)gridDim.x - 1) {
        __threadfence();
        double acc = 0.0;
        for (int i = lane; i < B; i += 32)
            acc += (double)((volatile float*)g_partial)[i];
#pragma unroll
        for (int o = 16; o; o >>= 1)
            acc += __shfl_xor_sync(FULL_MASK, acc, o);
        if (lane == 0) {
            out[0] = (float)acc;
            g_count = 0;   // reset for next graph replay
        }
    }
}

extern "C" void kernel_launch(void* const* d_in, const int* in_sizes, int n_in,
                              void* d_out, int out_size)
{
    const float* feats = (const float*)d_in[0];
    const float* trans = (const float*)d_in[1];
    const int*   tags  = (const int*)d_in[2];
    const int*   lens  = (const int*)d_in[3];
    float* out = (float*)d_out;

    int B = in_sizes[3];                  // word_seq_lens: (B,)
    int L = in_sizes[2] / B;              // tags: (B, L)

    sort_kernel<<<1, 1024>>>(lens, B, L);
    crf_nll_kernel<<<B / 2, 32>>>(feats, trans, tags, lens, out, B, L);
}

// round 4
// speedup vs baseline: 2.7877x; 2.7877x over previous
#include <cuda_runtime.h>
#include <cuda_bf16.h>
#include <cstdint>

#define FULL_MASK 0xFFFFFFFFu
#define TAGS 32
#define START 30
#define STOP 31

__device__ float g_partial[2048];
__device__ int   g_count = 0;

typedef unsigned long long ull;

// ---- packed fp32x2 helpers (Blackwell FFMA2 path, full fp32 precision) ----
__device__ __forceinline__ ull pack2(float lo, float hi) {
    ull r; asm("mov.b64 %0, {%1, %2};" : "=l"(r) : "f"(lo), "f"(hi)); return r;
}
__device__ __forceinline__ void unpack2(float& lo, float& hi, ull v) {
    asm("mov.b64 {%0, %1}, %2;" : "=f"(lo), "=f"(hi) : "l"(v));
}
__device__ __forceinline__ ull fma2(ull a, ull b, ull c) {
    ull r; asm("fma.rn.f32x2 %0, %1, %2, %3;" : "=l"(r) : "l"(a), "l"(b), "l"(c)); return r;
}
__device__ __forceinline__ ull mul2(ull a, ull b) {
    ull r; asm("mul.rn.f32x2 %0, %1, %2;" : "=l"(r) : "l"(a), "l"(b)); return r;
}
__device__ __forceinline__ ull add2(ull a, ull b) {
    ull r; asm("add.rn.f32x2 %0, %1, %2;" : "=l"(r) : "l"(a), "l"(b)); return r;
}
__device__ __forceinline__ void lds_v2u64(ull& a, ull& b, uint32_t addr) {
    asm volatile("ld.shared.v2.u64 {%0, %1}, [%2];" : "=l"(a), "=l"(b) : "r"(addr));
}

__global__ void __launch_bounds__(32, 16)
crf_nll_kernel(const float* __restrict__ feats,
               const float* __restrict__ trans,
               const int*   __restrict__ tags,
               const int*   __restrict__ lens,
               float* __restrict__ out,
               int B, int L)
{
    __shared__ __align__(16) float buf[2][TAGS];

    int b = blockIdx.x;
    int lane = threadIdx.x;

    const float* fb = feats + (size_t)b * L * TAGS;
    const int*   tb = tags  + (size_t)b * L;
    int len = lens[b];

    // lane j holds E column j packed in pairs: Ep[m] = (E[2m][j], E[2m+1][j])
    ull Ep[TAGS / 2];
#pragma unroll
    for (int m = 0; m < TAGS / 2; ++m) {
        float e0 = __expf(trans[(2 * m)     * TAGS + lane]);
        float e1 = __expf(trans[(2 * m + 1) * TAGS + lane]);
        Ep[m] = pack2(e0, e1);
    }
    float estop = __expf(trans[lane * TAGS + STOP]);

    // alpha0 -> exp-domain (one full max-reduce at start so p <= 1)
    float a0 = trans[START * TAGS + lane] + fb[lane];
    float m = a0;
#pragma unroll
    for (int o = 16; o; o >>= 1) m = fmaxf(m, __shfl_xor_sync(FULL_MASK, m, o));
    float p = __expf(a0 - m);
    float logscale = m;

    // feat prefetch ring (4 deep)
    float q0 = (1 < len) ? fb[1 * TAGS + lane] : 0.f;
    float q1 = (2 < len) ? fb[2 * TAGS + lane] : 0.f;
    float q2 = (3 < len) ? fb[3 * TAGS + lane] : 0.f;
    float q3 = (4 < len) ? fb[4 * TAGS + lane] : 0.f;

    uint32_t sb = (uint32_t)__cvta_generic_to_shared(&buf[0][0]);

#pragma unroll 4
    for (int t = 1; t < len; ++t) {
        float f = __expf(q0);                      // off the p-chain
        q0 = q1; q1 = q2; q2 = q3;
        q3 = (t + 4 < len) ? fb[(t + 4) * TAGS + lane] : 0.f;

        int slot = t & 1;
        buf[slot][lane] = p;
        __syncwarp();
        uint32_t base = sb + slot * (TAGS * 4);

        // packed matvec: 8x LDS.v2.u64 feeding 16 packed fma/mul
        ull c0, c1, c2, c3, c4, c5, c6, c7;
        {
            ull qa, qb;
            lds_v2u64(qa, qb, base +   0); c0 = fma2(qb, Ep[ 1], mul2(qa, Ep[ 0]));
            lds_v2u64(qa, qb, base +  16); c1 = fma2(qb, Ep[ 3], mul2(qa, Ep[ 2]));
            lds_v2u64(qa, qb, base +  32); c2 = fma2(qb, Ep[ 5], mul2(qa, Ep[ 4]));
            lds_v2u64(qa, qb, base +  48); c3 = fma2(qb, Ep[ 7], mul2(qa, Ep[ 6]));
            lds_v2u64(qa, qb, base +  64); c4 = fma2(qb, Ep[ 9], mul2(qa, Ep[ 8]));
            lds_v2u64(qa, qb, base +  80); c5 = fma2(qb, Ep[11], mul2(qa, Ep[10]));
            lds_v2u64(qa, qb, base +  96); c6 = fma2(qb, Ep[13], mul2(qa, Ep[12]));
            lds_v2u64(qa, qb, base + 112); c7 = fma2(qb, Ep[15], mul2(qa, Ep[14]));
        }
        ull d0 = add2(c0, c1), d1 = add2(c2, c3);
        ull d2 = add2(c4, c5), d3 = add2(c6, c7);
        ull g  = add2(add2(d0, d1), add2(d2, d3));
        float lo, hi;
        unpack2(lo, hi, g);
        p = (lo + hi) * f;

        // renorm every 4 steps by lane-0 value (p(lane0)=1 after renorm;
        // spread bound keeps everything within fp32 range)
        if ((t & 3) == 0) {
            float m0 = __shfl_sync(FULL_MASK, p, 0);
            p *= (1.0f / m0);
            logscale += __logf(m0);
        }
    }

    // forward score: logscale + log(sum_j p_j * exp(trans[j][STOP]))
    float v = p * estop;
#pragma unroll
    for (int o = 16; o; o >>= 1) v += __shfl_xor_sync(FULL_MASK, v, o);
    float fwd = logscale + __logf(v);

    // gold score (lane-strided gathers)
    float midsum = 0.f;
    for (int t = lane; t < len - 1; t += 32) {
        int tg  = tb[t];
        int tg1 = tb[t + 1];
        midsum += trans[tg * TAGS + tg1] + fb[(t + 1) * TAGS + tg1];
    }
#pragma unroll
    for (int o = 16; o; o >>= 1) midsum += __shfl_xor_sync(FULL_MASK, midsum, o);

    if (lane == 0) {
        int tag0 = tb[0];
        int tend = tb[len - 1];
        float gold = trans[START * TAGS + tag0] + fb[tag0]
                   + trans[tend * TAGS + STOP]
                   + midsum;
        g_partial[b] = fwd - gold;
    }

    // fused deterministic final reduction (last block to finish)
    __threadfence();
    int old = 0;
    if (lane == 0) old = atomicAdd(&g_count, 1);
    old = __shfl_sync(FULL_MASK, old, 0);
    if (old == B - 1) {
        __threadfence();
        double acc = 0.0;
        for (int i = lane; i < B; i += 32)
            acc += (double)((volatile float*)g_partial)[i];
#pragma unroll
        for (int o = 16; o; o >>= 1)
            acc += __shfl_xor_sync(FULL_MASK, acc, o);
        if (lane == 0) {
            out[0] = (float)acc;
            g_count = 0;   // reset for next graph replay
        }
    }
}

extern "C" void kernel_launch(void* const* d_in, const int* in_sizes, int n_in,
                              void* d_out, int out_size)
{
    const float* feats = (const float*)d_in[0];
    const float* trans = (const float*)d_in[1];
    const int*   tags  = (const int*)d_in[2];
    const int*   lens  = (const int*)d_in[3];
    float* out = (float*)d_out;

    int B = in_sizes[3];                  // word_seq_lens: (B,)
    int L = in_sizes[2] / B;              // tags: (B, L)

    crf_nll_kernel<<<B, 32>>>(feats, trans, tags, lens, out, B, L);
}